// round 10
// baseline (speedup 1.0000x reference)
#include <cuda_runtime.h>
#include <cuda_fp16.h>
#include <stdint.h>

// ---------------- problem constants ----------------
#define T_  20
#define S_  128
#define B_  32
#define H_  256
#define E_  128
#define V_  32000
#define N_  (S_*T_)      // 2560
#define NM_ (S_*7)       // 896 masked steps
#define ROWS_ (N_*B_)    // 81920
#define RQ_  (S_*B_)     // 4096

// ---------------- output layout (floats) ----------------
#define OFF_OUT   0ull
#define OFF_MEM1  131072000ull
#define OFF_MEM2  131080192ull
#define OFF_MEM3  131088384ull
#define OFF_D1    131096576ull
#define OFF_D2    131129344ull
#define OFF_D3    131194880ull
#define OFF_REC1  131260416ull
#define OFF_REC2  152231936ull
#define OFF_REC3  173203456ull

// ---------------- device scratch (static, no runtime alloc) ----------------
__device__ float  g_cur1[RQ_*H_];       //  4 MB  layer-1 currents per token
__device__ float  g_cur [N_*B_*H_];     // 84 MB  currents (reused layer2/3)
__device__ __half g_woutcat[V_*512];    // 32 MB  [v][0:256]=hi fp16, [256:512]=lo fp16
__device__ __half g_poolh[RQ_*H_];      // spike counts 0..20, exact in fp16
__device__ float  g_xm[S_*E_];
__device__ float  g_xmrep[NM_*E_];
__device__ float  g_pm1[NM_*H_];
__device__ float  g_pm2[NM_*H_];
__device__ float  g_pm3[NM_*H_];

// ---------------- Wout -> fp16 hi/lo split ----------------
__global__ void k_conv_wout(const float* __restrict__ Wout) {
    int i = blockIdx.x * blockDim.x + threadIdx.x;
    if (i >= V_*H_) return;
    int v = i >> 8, k = i & 255;
    float w  = Wout[i];
    __half hi = __float2half(w);
    float lo = w - __half2float(hi);
    g_woutcat[(size_t)v*512 + k]       = hi;
    g_woutcat[(size_t)v*512 + 256 + k] = __float2half(lo);
}

// ---------------- layer-1 currents (fp32, sequential k) + batch-mean embedding ----------------
__global__ __launch_bounds__(256) void k_cur1(const int* __restrict__ x,
                                              const float* __restrict__ embed,
                                              const float* __restrict__ W1,
                                              const float* __restrict__ b1) {
    int s = blockIdx.x;
    __shared__ float semb[B_][E_];
    int tid = threadIdx.x;
    for (int u = tid; u < B_*E_; u += 256) {
        int b = u >> 7, e = u & 127;
        semb[b][e] = embed[(size_t)x[b*S_ + s] * E_ + e];
    }
    __syncthreads();
    int h = tid;
    float acc[B_];
#pragma unroll
    for (int b = 0; b < B_; b++) acc[b] = 0.f;
    for (int e = 0; e < E_; e++) {            // strictly increasing k, fp32 FMA
        float w = W1[h*E_ + e];
#pragma unroll
        for (int b = 0; b < B_; b++) acc[b] = fmaf(semb[b][e], w, acc[b]);
    }
    float bb = b1[h];
#pragma unroll
    for (int b = 0; b < B_; b++)
        g_cur1[((s*B_ + b) << 8) + h] = acc[b] + bb;

    if (tid < E_) {                            // batch mean, sequential b order
        float sum = 0.f;
#pragma unroll
        for (int b = 0; b < B_; b++) sum += semb[b][tid];
        g_xm[s*E_ + tid] = sum * (1.0f/32.0f);
    }
}

__global__ void k_xmrep() {
    int i = blockIdx.x * blockDim.x + threadIdx.x;
    if (i >= NM_*E_) return;
    int m = i / E_, e = i % E_;
    g_xmrep[i] = g_xm[(m/7)*E_ + e];
}

// ---------------- LIF recurrence (elementwise, 2560 steps) ----------------
// R8 CHANGE: membrane update uses FUSED multiply-add, matching XLA's
// fp-contraction of (BETA*mem + cur):   mem = fma(0.85, mem, cur) - spk
template <int LAYER>
__global__ __launch_bounds__(128) void k_recur(float* __restrict__ rec,
                                               float* __restrict__ memOut) {
    int b = threadIdx.x;                         // lane = batch
    int h = blockIdx.x * blockDim.y + threadIdx.y;
    float* pm = (LAYER == 1) ? g_pm1 : (LAYER == 2 ? g_pm2 : g_pm3);

    float mem = 0.f, spk = 0.f, pc = 0.f;
    size_t idx = (size_t)b * H_ + h;             // advances by B*H per step

    for (int s = 0; s < S_; s++) {
        float curTok = 0.f;
        if (LAYER == 1) curTok = g_cur1[(size_t)(s*B_ + b)*H_ + h];
#pragma unroll 4
        for (int t = 0; t < T_; t++) {
            float cur = (LAYER == 1) ? curTok : g_cur[idx];
            // fma(BETA, mem, cur) - reset  with reset == previous spike (THR=1)
            mem = __fsub_rn(__fmaf_rn(0.85f, mem, cur), spk);
            spk = (mem > 1.0f) ? 1.0f : 0.0f;
            rec[idx] = spk;                       // spikes reused as GEMM A operand
            if (LAYER == 3) pc += spk;
            if (t % 3 == 0) {
                float v = spk;                    // integer sum: order-exact
#pragma unroll
                for (int o = 16; o; o >>= 1) v += __shfl_xor_sync(0xffffffffu, v, o);
                if (b == 0) pm[(s*7 + t/3)*H_ + h] = v * (1.0f/32.0f);
            }
            idx += B_*H_;
        }
        if (LAYER == 3) {
            g_poolh[(size_t)(s*B_ + b)*H_ + h] = __float2half(pc);  // exact int
            pc = 0.f;
        }
    }
    memOut[b*H_ + h] = mem;
}

// ---------------- mid GEMM (fp32, sequential-k FMA per element) ----------------
// g_cur[81920,256] = A[81920,256]{0,1} * W[256,256]^T + bias, acc order k=0..255
// NOTE: writes g_cur via the device symbol (never pass a __device__ symbol
// from host code — that was the R4/R6 failure).
__global__ __launch_bounds__(256) void k_gemm_mid_f32(const float* __restrict__ A,
                                                      const float* __restrict__ W,
                                                      const float* __restrict__ bias) {
    __shared__ float sA[16][68];   // [k][m]
    __shared__ float sB[16][68];   // [k][n]
    const int bn = blockIdx.x, bm = blockIdx.y;
    const int tid = threadIdx.x;
    const int tx = tid & 15, ty = tid >> 4;      // 16x16 threads, 4x4 outputs each
    const int lrow = tid >> 2, lkg = (tid & 3) * 4;

    float acc[4][4] = {};

    for (int kt = 0; kt < 256; kt += 16) {
        // load A tile [64m x 16k] and W tile [64n x 16k], transposed into smem
        float4 av = *(const float4*)&A[(size_t)(bm*64 + lrow)*256 + kt + lkg];
        float4 bv = *(const float4*)&W[(size_t)(bn*64 + lrow)*256 + kt + lkg];
        sA[lkg+0][lrow] = av.x; sA[lkg+1][lrow] = av.y;
        sA[lkg+2][lrow] = av.z; sA[lkg+3][lrow] = av.w;
        sB[lkg+0][lrow] = bv.x; sB[lkg+1][lrow] = bv.y;
        sB[lkg+2][lrow] = bv.z; sB[lkg+3][lrow] = bv.w;
        __syncthreads();
#pragma unroll
        for (int k = 0; k < 16; k++) {           // strictly increasing k
            float4 a = *(const float4*)&sA[k][ty*4];
            float4 b = *(const float4*)&sB[k][tx*4];
            float ar[4] = {a.x, a.y, a.z, a.w};
            float br[4] = {b.x, b.y, b.z, b.w};
#pragma unroll
            for (int i = 0; i < 4; i++)
#pragma unroll
                for (int j = 0; j < 4; j++)
                    acc[i][j] = fmaf(ar[i], br[j], acc[i][j]);
        }
        __syncthreads();
    }
#pragma unroll
    for (int i = 0; i < 4; i++) {
        size_t r = (size_t)(bm*64 + ty*4 + i);
#pragma unroll
        for (int j = 0; j < 4; j++) {
            int n = bn*64 + tx*4 + j;
            g_cur[r*256 + n] = acc[i][j] + bias[n];
        }
    }
}

// ---------------- fp16 mma.sync m16n8k16 helper ----------------
__device__ __forceinline__ void mma16816(float* d, const uint32_t* a, const uint32_t* b) {
    asm volatile(
        "mma.sync.aligned.m16n8k16.row.col.f32.f16.f16.f32 "
        "{%0,%1,%2,%3},{%4,%5,%6,%7},{%8,%9},{%0,%1,%2,%3};\n"
        : "+f"(d[0]), "+f"(d[1]), "+f"(d[2]), "+f"(d[3])
        : "r"(a[0]), "r"(a[1]), "r"(a[2]), "r"(a[3]), "r"(b[0]), "r"(b[1]));
}

// ---------------- output GEMM: out = (counts . (Whi+Wlo))/20 + bout ----------------
// C[4096,32000] = A[4096,256] (counts, dup over K halves) * Wcat[32000,512]
__global__ __launch_bounds__(256) void k_gemm_out(const float* __restrict__ bout,
                                                  float* __restrict__ out) {
    __shared__ __half sA[64*72];
    __shared__ __half sB[64*72];
    const int bn = blockIdx.x, bm = blockIdx.y;
    const int tid = threadIdx.x;
    const int warp = tid >> 5, lane = tid & 31;
    const int wm = warp >> 2, wn = warp & 3;
    const int g = lane >> 2, tg = lane & 3;

    float acc[2][2][4] = {};

    for (int kc = 0; kc < 512; kc += 64) {
        int ak = kc & 255;   // counts repeat over the hi/lo halves
        for (int u = tid; u < 512; u += 256) {
            int row = u >> 3, c8 = (u & 7) * 8;
            *(uint4*)&sA[row*72 + c8] =
                *(const uint4*)&g_poolh[(size_t)(bm*64 + row)*256 + ak + c8];
            *(uint4*)&sB[row*72 + c8] =
                *(const uint4*)&g_woutcat[(size_t)(bn*64 + row)*512 + kc + c8];
        }
        __syncthreads();
#pragma unroll
        for (int kk = 0; kk < 64; kk += 16) {
            uint32_t afr[2][4], bfr[2][2];
#pragma unroll
            for (int mi = 0; mi < 2; mi++) {
                const __half* p = &sA[(wm*32 + mi*16 + g)*72 + kk + tg*2];
                afr[mi][0] = *(const uint32_t*)p;
                afr[mi][1] = *(const uint32_t*)(p + 8*72);
                afr[mi][2] = *(const uint32_t*)(p + 8);
                afr[mi][3] = *(const uint32_t*)(p + 8*72 + 8);
            }
#pragma unroll
            for (int ni = 0; ni < 2; ni++) {
                const __half* p = &sB[(wn*16 + ni*8 + g)*72 + kk + tg*2];
                bfr[ni][0] = *(const uint32_t*)p;
                bfr[ni][1] = *(const uint32_t*)(p + 8);
            }
#pragma unroll
            for (int mi = 0; mi < 2; mi++)
#pragma unroll
                for (int ni = 0; ni < 2; ni++)
                    mma16816(acc[mi][ni], afr[mi], bfr[ni]);
        }
        __syncthreads();
    }
    const float inv = 1.0f/20.0f;
#pragma unroll
    for (int mi = 0; mi < 2; mi++) {
        int r = bm*64 + wm*32 + mi*16 + g;     // r = s*32 + b ; (r&31)+8 stays < 32
        int s = r >> 5, bb = r & 31;
        size_t base  = (size_t)bb*(size_t)S_*V_ + (size_t)s*V_;
        size_t base8 = base + (size_t)8*(size_t)S_*V_;
#pragma unroll
        for (int ni = 0; ni < 2; ni++) {
            int v = bn*64 + wn*16 + ni*8 + tg*2;
            float b0 = bout[v], b1v = bout[v+1];
            out[base  + v]     = acc[mi][ni][0]*inv + b0;
            out[base  + v + 1] = acc[mi][ni][1]*inv + b1v;
            out[base8 + v]     = acc[mi][ni][2]*inv + b0;
            out[base8 + v + 1] = acc[mi][ni][3]*inv + b1v;
        }
    }
}

// ---------------- STDP: d[o,i] = sum_m (A_POST*post)[m,o]*(A_PRE*pre)[m,i] ----------------
__global__ void k_stdp(int sel, float* __restrict__ Dout, int I) {
    const float* Amat = (sel == 0) ? g_pm1 : (sel == 1 ? g_pm2 : g_pm3);
    const float* Bmat = (sel == 0) ? g_xmrep : (sel == 1 ? g_pm1 : g_pm2);
    int o = blockIdx.x;
    int i = threadIdx.x;
    float acc = 0.f;
    for (int m = 0; m < NM_; m++) {
        float a = __fmul_rn(-0.003f, __ldg(&Amat[m*H_ + o]));  // A_POST * post
        float b = __fmul_rn( 0.005f, __ldg(&Bmat[m*I + i]));   // A_PRE * pre
        acc = fmaf(a, b, acc);
    }
    Dout[o*I + i] = acc;
}

// ---------------- launch ----------------
// RULE: never pass a __device__ symbol (g_*) as a kernel argument from here.
extern "C" void kernel_launch(void* const* d_in, const int* in_sizes, int n_in,
                              void* d_out, int out_size) {
    const int*   x     = (const int*)  d_in[0];
    const float* embed = (const float*)d_in[1];
    const float* W1    = (const float*)d_in[2];
    const float* b1    = (const float*)d_in[3];
    const float* W2    = (const float*)d_in[4];
    const float* b2    = (const float*)d_in[5];
    const float* W3    = (const float*)d_in[6];
    const float* b3    = (const float*)d_in[7];
    const float* Wout  = (const float*)d_in[8];
    const float* bout  = (const float*)d_in[9];
    float* out = (float*)d_out;

    (void)in_sizes; (void)n_in; (void)out_size;

    // Wout hi/lo conversion
    k_conv_wout<<<(V_*H_ + 255)/256, 256>>>(Wout);

    // layer-1 currents (raw fp32, sequential k) + batch-mean embeddings
    k_cur1 <<<S_, 256>>>(x, embed, W1, b1);
    k_xmrep<<<(NM_*E_ + 255)/256, 256>>>();

    dim3 rblk(32, 4);
    // layer 1 (spikes written straight into rec1 — reused as GEMM A operand)
    k_recur<1><<<H_/4, rblk>>>(out + OFF_REC1, out + OFF_MEM1);
    // cur2 = spk1 @ W2.T + b2  (fp32, sequential-k; writes g_cur internally)
    k_gemm_mid_f32<<<dim3(H_/64, ROWS_/64), 256>>>(out + OFF_REC1, W2, b2);
    // layer 2
    k_recur<2><<<H_/4, rblk>>>(out + OFF_REC2, out + OFF_MEM2);
    // cur3 = spk2 @ W3.T + b3
    k_gemm_mid_f32<<<dim3(H_/64, ROWS_/64), 256>>>(out + OFF_REC2, W3, b3);
    // layer 3 (also builds pooled spike counts)
    k_recur<3><<<H_/4, rblk>>>(out + OFF_REC3, out + OFF_MEM3);

    // out = pooled @ Wout.T + bout  (fp16 hi/lo tensor cores, /20 in epilogue)
    k_gemm_out<<<dim3(V_/64, RQ_/64), 256>>>(bout, out + OFF_OUT);

    // STDP
    k_stdp<<<H_, E_>>>(0, out + OFF_D1, E_);
    k_stdp<<<H_, H_>>>(1, out + OFF_D2, H_);
    k_stdp<<<H_, H_>>>(2, out + OFF_D3, H_);
}

// round 11
// speedup vs baseline: 1.3546x; 1.3546x over previous
#include <cuda_runtime.h>
#include <cuda_fp16.h>
#include <stdint.h>

// ---------------- problem constants ----------------
#define T_  20
#define S_  128
#define B_  32
#define H_  256
#define E_  128
#define V_  32000
#define N_  (S_*T_)      // 2560
#define NM_ (S_*7)       // 896 masked steps
#define ROWS_ (N_*B_)    // 81920
#define RQ_  (S_*B_)     // 4096

// ---------------- output layout (floats) ----------------
#define OFF_OUT   0ull
#define OFF_MEM1  131072000ull
#define OFF_MEM2  131080192ull
#define OFF_MEM3  131088384ull
#define OFF_D1    131096576ull
#define OFF_D2    131129344ull
#define OFF_D3    131194880ull
#define OFF_REC1  131260416ull
#define OFF_REC2  152231936ull
#define OFF_REC3  173203456ull

// ---------------- device scratch (static, no runtime alloc) ----------------
__device__ float    g_cur1[RQ_*H_];      //  4 MB  layer-1 currents per token
__device__ float    g_cur [N_*B_*H_];    // 84 MB  currents (reused layer2/3)
__device__ __half   g_woutcat[V_*512];   // 32 MB  [v][0:256]=hi, [256:512]=lo
__device__ __half   g_poolh[RQ_*H_];     // spike counts 0..20, exact in fp16
__device__ float    g_wt2[H_*H_];        // W2 transposed [k][n]
__device__ float    g_wt3[H_*H_];        // W3 transposed [k][n]
__device__ unsigned g_mask[ROWS_*8];     // 2.6 MB spike bitmasks (reused L1/L2 spikes)
__device__ float    g_xm[S_*E_];
__device__ float    g_xmrep[NM_*E_];
__device__ float    g_pm1[NM_*H_];
__device__ float    g_pm2[NM_*H_];
__device__ float    g_pm3[NM_*H_];

// ---------------- Wout -> fp16 hi/lo split ----------------
__global__ void k_conv_wout(const float* __restrict__ Wout) {
    int i = blockIdx.x * blockDim.x + threadIdx.x;
    if (i >= V_*H_) return;
    int v = i >> 8, k = i & 255;
    float w  = Wout[i];
    __half hi = __float2half(w);
    float lo = w - __half2float(hi);
    g_woutcat[(size_t)v*512 + k]       = hi;
    g_woutcat[(size_t)v*512 + 256 + k] = __float2half(lo);
}

// ---------------- W2/W3 transpose [n][k] -> [k][n] ----------------
__global__ void k_conv_wt(const float* __restrict__ W2, const float* __restrict__ W3) {
    int i = blockIdx.x * blockDim.x + threadIdx.x;   // i = k*256 + n
    if (i >= H_*H_) return;
    int n = i & 255, k = i >> 8;
    g_wt2[i] = W2[n*256 + k];
    g_wt3[i] = W3[n*256 + k];
}

// ---------------- layer-1 currents (fp32, sequential k) + batch-mean embedding ----------------
__global__ __launch_bounds__(256) void k_cur1(const int* __restrict__ x,
                                              const float* __restrict__ embed,
                                              const float* __restrict__ W1,
                                              const float* __restrict__ b1) {
    int s = blockIdx.x;
    __shared__ float semb[B_][E_];
    int tid = threadIdx.x;
    for (int u = tid; u < B_*E_; u += 256) {
        int b = u >> 7, e = u & 127;
        semb[b][e] = embed[(size_t)x[b*S_ + s] * E_ + e];
    }
    __syncthreads();
    int h = tid;
    float acc[B_];
#pragma unroll
    for (int b = 0; b < B_; b++) acc[b] = 0.f;
    for (int e = 0; e < E_; e++) {            // strictly increasing k, fp32 FMA
        float w = W1[h*E_ + e];
#pragma unroll
        for (int b = 0; b < B_; b++) acc[b] = fmaf(semb[b][e], w, acc[b]);
    }
    float bb = b1[h];
#pragma unroll
    for (int b = 0; b < B_; b++)
        g_cur1[((s*B_ + b) << 8) + h] = acc[b] + bb;

    if (tid < E_) {                            // batch mean, sequential b order
        float sum = 0.f;
#pragma unroll
        for (int b = 0; b < B_; b++) sum += semb[b][tid];
        g_xm[s*E_ + tid] = sum * (1.0f/32.0f);
    }
}

__global__ void k_xmrep() {
    int i = blockIdx.x * blockDim.x + threadIdx.x;
    if (i >= NM_*E_) return;
    int m = i / E_, e = i % E_;
    g_xmrep[i] = g_xm[(m/7)*E_ + e];
}

// ---------------- LIF recurrence (coalesced: lane = h) ----------------
// mem = fma(0.85, mem, cur) - spk  (bit-identical to R8/R10 pass)
// Also emits spike bitmasks (LAYER 1,2) for the sparse GEMMs.
template <int LAYER>
__global__ __launch_bounds__(128) void k_recur(float* __restrict__ rec,
                                               float* __restrict__ memOut) {
    int lane = threadIdx.x;                       // h within 32-tile
    int h = blockIdx.x * 32 + lane;
    int b = blockIdx.y * 4 + threadIdx.y;

    float mem = 0.f, spk = 0.f, pc = 0.f;
    size_t base = (size_t)b * H_ + h;
    size_t idx  = base;                           // advances by B*H per step
    int step = 0;

    for (int s = 0; s < S_; s++) {
        float curTok = 0.f;
        if (LAYER == 1) curTok = g_cur1[(size_t)(s*B_ + b)*H_ + h];
#pragma unroll 4
        for (int t = 0; t < T_; t++) {
            float cur = (LAYER == 1) ? curTok : g_cur[idx];
            mem = __fsub_rn(__fmaf_rn(0.85f, mem, cur), spk);
            bool fire = (mem > 1.0f);
            spk = fire ? 1.0f : 0.0f;
            rec[idx] = spk;                       // coalesced 128B per warp
            if (LAYER <= 2) {
                unsigned msk = __ballot_sync(0xffffffffu, fire);
                if (lane == 0) g_mask[(size_t)(step*B_ + b)*8 + blockIdx.x] = msk;
            }
            if (LAYER == 3) pc += spk;
            idx += B_*H_;
            step++;
        }
        if (LAYER == 3) {
            g_poolh[(size_t)(s*B_ + b)*H_ + h] = __float2half(pc);  // exact int
            pc = 0.f;
        }
    }
    memOut[base] = mem;
}

// ---------------- batch-mean spikes at masked steps (exact int sums) ----------------
__global__ __launch_bounds__(256) void k_pm(int sel, const float* __restrict__ rec) {
    float* pm = (sel == 0) ? g_pm1 : (sel == 1 ? g_pm2 : g_pm3);
    int m = blockIdx.x;               // 0..NM_-1
    int h = threadIdx.x;
    int step = (m/7)*T_ + (m%7)*3;
    const float* p = rec + (size_t)step*B_*H_ + h;
    float sum = 0.f;
#pragma unroll
    for (int b = 0; b < B_; b++) sum += p[(size_t)b*H_];   // 0/1 ints: order-free exact
    pm[m*H_ + h] = sum * (1.0f/32.0f);
}

// ---------------- sparse mid GEMM: cur = spk @ W.T + bias ----------------
// Bitwise identical to dense sequential-k fp32: fmaf(0,w,a)=a, fmaf(1,w,a)=RN(a+w).
// Adds selected weights in strictly increasing k (LSB-first within ascending k-tiles).
__global__ __launch_bounds__(256) void k_gemm_sp(int wsel, const float* __restrict__ bias) {
    const float* WT = (wsel == 0) ? g_wt2 : g_wt3;   // [k][n]
    __shared__ float    sW[32*256];                  // 32 KB k-tile
    __shared__ unsigned sM[32];
    const int row0 = blockIdx.x * 32;
    const int n = threadIdx.x;

    float acc[32];
#pragma unroll
    for (int r = 0; r < 32; r++) acc[r] = 0.f;
    float bb = bias[n];

    for (int kt = 0; kt < 8; kt++) {
        // load W k-tile [32k][256n]
        const float4* src = (const float4*)(WT + kt*32*256);
        float4* dst = (float4*)sW;
        for (int i = n; i < 32*64; i += 256) dst[i] = src[i];
        if (n < 32) sM[n] = g_mask[(size_t)(row0 + n)*8 + kt];
        __syncthreads();
#pragma unroll
        for (int r = 0; r < 32; r++) {
            unsigned m = sM[r];
            while (m) {
                int k = __ffs(m) - 1;   // smallest set k first (ascending order)
                m &= m - 1;
                acc[r] = __fadd_rn(acc[r], sW[k*256 + n]);
            }
        }
        __syncthreads();
    }
#pragma unroll
    for (int r = 0; r < 32; r++)
        g_cur[(size_t)(row0 + r)*256 + n] = acc[r] + bb;
}

// ---------------- fp16 mma.sync m16n8k16 + ldmatrix helpers ----------------
__device__ __forceinline__ void mma16816(float* d, const uint32_t* a, const uint32_t* b) {
    asm volatile(
        "mma.sync.aligned.m16n8k16.row.col.f32.f16.f16.f32 "
        "{%0,%1,%2,%3},{%4,%5,%6,%7},{%8,%9},{%0,%1,%2,%3};\n"
        : "+f"(d[0]), "+f"(d[1]), "+f"(d[2]), "+f"(d[3])
        : "r"(a[0]), "r"(a[1]), "r"(a[2]), "r"(a[3]), "r"(b[0]), "r"(b[1]));
}
__device__ __forceinline__ void ldsm_x4(uint32_t* r, const __half* p) {
    uint32_t a = (uint32_t)__cvta_generic_to_shared((void*)p);
    asm volatile("ldmatrix.sync.aligned.m8n8.x4.shared.b16 {%0,%1,%2,%3}, [%4];"
        : "=r"(r[0]), "=r"(r[1]), "=r"(r[2]), "=r"(r[3]) : "r"(a));
}

// ---------------- output GEMM: out = (counts . (Whi+Wlo))/20 + bout ----------------
// 128m x 64n tile, ldmatrix frag loads. K=512 concat (counts duplicated).
__global__ __launch_bounds__(256) void k_gemm_out(const float* __restrict__ bout,
                                                  float* __restrict__ out) {
    __shared__ __half sA[128*72];
    __shared__ __half sB[64*72];
    const int bn = blockIdx.x, bm = blockIdx.y;
    const int tid = threadIdx.x;
    const int warp = tid >> 5, lane = tid & 31;
    const int wm = warp >> 1, wn = warp & 1;       // 4 x 2 warps -> 32m x 32n each
    const int g = lane >> 2, tg = lane & 3;
    const int rsel = (lane & 7) | (lane & 8);      // ldmatrix row within 16
    const int csel = (lane >> 4) << 3;             // ldmatrix k-half select

    float acc[2][4][4] = {};

    for (int kc = 0; kc < 512; kc += 64) {
        int ak = kc & 255;   // counts repeat over the hi/lo halves
        for (int u = tid; u < 1024; u += 256) {    // A: 128 rows x 64 halfs
            int row = u >> 3, c8 = (u & 7) * 8;
            *(uint4*)&sA[row*72 + c8] =
                *(const uint4*)&g_poolh[(size_t)(bm*128 + row)*256 + ak + c8];
        }
        for (int u = tid; u < 512; u += 256) {     // B: 64 rows x 64 halfs
            int row = u >> 3, c8 = (u & 7) * 8;
            *(uint4*)&sB[row*72 + c8] =
                *(const uint4*)&g_woutcat[(size_t)(bn*64 + row)*512 + kc + c8];
        }
        __syncthreads();
#pragma unroll
        for (int kk = 0; kk < 64; kk += 16) {
            uint32_t afr[2][4], bq[2][4];
#pragma unroll
            for (int mi = 0; mi < 2; mi++)
                ldsm_x4(afr[mi], &sA[(wm*32 + mi*16 + rsel)*72 + kk + csel]);
#pragma unroll
            for (int hb = 0; hb < 2; hb++)
                ldsm_x4(bq[hb], &sB[(wn*32 + hb*16 + rsel)*72 + kk + csel]);
#pragma unroll
            for (int mi = 0; mi < 2; mi++)
#pragma unroll
                for (int ni = 0; ni < 4; ni++) {
                    uint32_t bfr[2] = { bq[ni>>1][ni&1], bq[ni>>1][2 + (ni&1)] };
                    mma16816(acc[mi][ni], afr[mi], bfr);
                }
        }
        __syncthreads();
    }
    const float inv = 1.0f/20.0f;
#pragma unroll
    for (int mi = 0; mi < 2; mi++) {
        int r = bm*128 + wm*32 + mi*16 + g;   // r = s*32 + b ; (r&31)+8 stays < 32
        int s = r >> 5, bb = r & 31;
        size_t base  = (size_t)bb*(size_t)S_*V_ + (size_t)s*V_;
        size_t base8 = base + (size_t)8*(size_t)S_*V_;
#pragma unroll
        for (int ni = 0; ni < 4; ni++) {
            int v = bn*64 + wn*32 + ni*8 + tg*2;
            float b0 = bout[v], b1v = bout[v+1];
            out[base  + v]     = acc[mi][ni][0]*inv + b0;
            out[base  + v + 1] = acc[mi][ni][1]*inv + b1v;
            out[base8 + v]     = acc[mi][ni][2]*inv + b0;
            out[base8 + v + 1] = acc[mi][ni][3]*inv + b1v;
        }
    }
}

// ---------------- STDP: d[o,i] = sum_m (A_POST*post)[m,o]*(A_PRE*pre)[m,i] ----------------
__global__ void k_stdp(int sel, float* __restrict__ Dout, int I) {
    const float* Amat = (sel == 0) ? g_pm1 : (sel == 1 ? g_pm2 : g_pm3);
    const float* Bmat = (sel == 0) ? g_xmrep : (sel == 1 ? g_pm1 : g_pm2);
    int o = blockIdx.x;
    int i = threadIdx.x;
    float acc = 0.f;
    for (int m = 0; m < NM_; m++) {
        float a = __fmul_rn(-0.003f, __ldg(&Amat[m*H_ + o]));  // A_POST * post
        float b = __fmul_rn( 0.005f, __ldg(&Bmat[m*I + i]));   // A_PRE * pre
        acc = fmaf(a, b, acc);
    }
    Dout[o*I + i] = acc;
}

// ---------------- launch ----------------
// RULE: never pass a __device__ symbol (g_*) as a kernel argument from here.
extern "C" void kernel_launch(void* const* d_in, const int* in_sizes, int n_in,
                              void* d_out, int out_size) {
    const int*   x     = (const int*)  d_in[0];
    const float* embed = (const float*)d_in[1];
    const float* W1    = (const float*)d_in[2];
    const float* b1    = (const float*)d_in[3];
    const float* W2    = (const float*)d_in[4];
    const float* b2    = (const float*)d_in[5];
    const float* W3    = (const float*)d_in[6];
    const float* b3    = (const float*)d_in[7];
    const float* Wout  = (const float*)d_in[8];
    const float* bout  = (const float*)d_in[9];
    float* out = (float*)d_out;

    (void)in_sizes; (void)n_in; (void)out_size;

    // weight prep
    k_conv_wout<<<(V_*H_ + 255)/256, 256>>>(Wout);
    k_conv_wt  <<<(H_*H_ + 255)/256, 256>>>(W2, W3);

    // layer-1 currents (raw fp32, sequential k) + batch-mean embeddings
    k_cur1 <<<S_, 256>>>(x, embed, W1, b1);
    k_xmrep<<<(NM_*E_ + 255)/256, 256>>>();

    dim3 rgrid(H_/32, B_/4), rblk(32, 4);
    // layer 1
    k_recur<1><<<rgrid, rblk>>>(out + OFF_REC1, out + OFF_MEM1);
    k_pm<<<NM_, 256>>>(0, out + OFF_REC1);
    // cur2 = spk1 @ W2.T + b2  (sparse, bit-exact sequential-k)
    k_gemm_sp<<<ROWS_/32, 256>>>(0, b2);
    // layer 2
    k_recur<2><<<rgrid, rblk>>>(out + OFF_REC2, out + OFF_MEM2);
    k_pm<<<NM_, 256>>>(1, out + OFF_REC2);
    // cur3 = spk2 @ W3.T + b3
    k_gemm_sp<<<ROWS_/32, 256>>>(1, b3);
    // layer 3 (also builds pooled spike counts)
    k_recur<3><<<rgrid, rblk>>>(out + OFF_REC3, out + OFF_MEM3);
    k_pm<<<NM_, 256>>>(2, out + OFF_REC3);

    // out = pooled @ Wout.T + bout  (fp16 hi/lo tensor cores, /20 in epilogue)
    k_gemm_out<<<dim3(V_/64, RQ_/128), 256>>>(bout, out + OFF_OUT);

    // STDP
    k_stdp<<<H_, E_>>>(0, out + OFF_D1, E_);
    k_stdp<<<H_, H_>>>(1, out + OFF_D2, H_);
    k_stdp<<<H_, H_>>>(2, out + OFF_D3, H_);
}

// round 12
// speedup vs baseline: 3.0993x; 2.2880x over previous
#include <cuda_runtime.h>
#include <cuda_fp16.h>
#include <stdint.h>

// ---------------- problem constants ----------------
#define T_  20
#define S_  128
#define B_  32
#define H_  256
#define E_  128
#define V_  32000
#define N_  (S_*T_)      // 2560
#define NM_ (S_*7)       // 896 masked steps
#define ROWS_ (N_*B_)    // 81920
#define RQ_  (S_*B_)     // 4096
#define BH_ (B_*H_)

// ---------------- output layout (floats) ----------------
#define OFF_OUT   0ull
#define OFF_MEM1  131072000ull
#define OFF_MEM2  131080192ull
#define OFF_MEM3  131088384ull
#define OFF_D1    131096576ull
#define OFF_D2    131129344ull
#define OFF_D3    131194880ull
#define OFF_REC1  131260416ull
#define OFF_REC2  152231936ull
#define OFF_REC3  173203456ull

// ---------------- device scratch (static, no runtime alloc) ----------------
__device__ float    g_cur1[RQ_*H_];      //  4 MB  layer-1 currents per token
__device__ float    g_cur [N_*B_*H_];    // 84 MB  currents (reused layer2/3)
__device__ __half   g_wouth[V_*H_];      // 16 MB  fp16 Wout
__device__ __half   g_poolh[RQ_*H_];     // spike counts 0..20, exact in fp16
__device__ float    g_wt2[H_*H_];        // W2 transposed [k][n]
__device__ float    g_wt3[H_*H_];        // W3 transposed [k][n]
__device__ unsigned g_mask[ROWS_*8];     // 2.6 MB spike bitmasks
__device__ float    g_xm[S_*E_];
__device__ float    g_xmrep[NM_*E_];
__device__ float    g_pm1[NM_*H_];
__device__ float    g_pm2[NM_*H_];
__device__ float    g_pm3[NM_*H_];

// ---------------- Wout -> fp16 ----------------
__global__ void k_conv_wout(const float* __restrict__ Wout) {
    int i = blockIdx.x * blockDim.x + threadIdx.x;
    if (i < V_*H_) g_wouth[i] = __float2half(Wout[i]);
}

// ---------------- W2/W3 transpose [n][k] -> [k][n] ----------------
__global__ void k_conv_wt(const float* __restrict__ W2, const float* __restrict__ W3) {
    int i = blockIdx.x * blockDim.x + threadIdx.x;   // i = k*256 + n
    if (i >= H_*H_) return;
    int n = i & 255, k = i >> 8;
    g_wt2[i] = W2[n*256 + k];
    g_wt3[i] = W3[n*256 + k];
}

// ---------------- layer-1 currents (fp32, sequential k) + batch-mean embedding ----------------
__global__ __launch_bounds__(256) void k_cur1(const int* __restrict__ x,
                                              const float* __restrict__ embed,
                                              const float* __restrict__ W1,
                                              const float* __restrict__ b1) {
    int s = blockIdx.x;
    __shared__ float semb[B_][E_];
    int tid = threadIdx.x;
    for (int u = tid; u < B_*E_; u += 256) {
        int b = u >> 7, e = u & 127;
        semb[b][e] = embed[(size_t)x[b*S_ + s] * E_ + e];
    }
    __syncthreads();
    int h = tid;
    float acc[B_];
#pragma unroll
    for (int b = 0; b < B_; b++) acc[b] = 0.f;
    for (int e = 0; e < E_; e++) {            // strictly increasing k, fp32 FMA
        float w = W1[h*E_ + e];
#pragma unroll
        for (int b = 0; b < B_; b++) acc[b] = fmaf(semb[b][e], w, acc[b]);
    }
    float bb = b1[h];
#pragma unroll
    for (int b = 0; b < B_; b++)
        g_cur1[((s*B_ + b) << 8) + h] = acc[b] + bb;

    if (tid < E_) {                            // batch mean, sequential b order
        float sum = 0.f;
#pragma unroll
        for (int b = 0; b < B_; b++) sum += semb[b][tid];
        g_xm[s*E_ + tid] = sum * (1.0f/32.0f);
    }
}

__global__ void k_xmrep() {
    int i = blockIdx.x * blockDim.x + threadIdx.x;
    if (i >= NM_*E_) return;
    int m = i / E_, e = i % E_;
    g_xmrep[i] = g_xm[(m/7)*E_ + e];
}

// ---------------- LIF recurrence: 1 warp/block, software-pipelined prefetch ----------
// mem = fma(0.85, mem, cur) - spk  (bit-identical ops/order to passing version)
template <int LAYER>
__global__ __launch_bounds__(32) void k_recur(float* __restrict__ rec,
                                              float* __restrict__ memOut) {
    const int lane = threadIdx.x;
    const int ht = blockIdx.x & 7;           // h tile
    const int b  = blockIdx.x >> 3;          // batch
    const int h  = ht*32 + lane;

    float mem = 0.f, spk = 0.f, pc = 0.f;
    const size_t base = (size_t)b * H_ + h;
    size_t idx = base;

    float cbufA[T_], cbufB[T_];
    float tokA = 0.f, tokB = 0.f;

    // preload token 0
    if (LAYER == 1) {
        tokA = g_cur1[(size_t)(0*B_ + b)*H_ + h];
    } else {
#pragma unroll
        for (int t = 0; t < T_; t++) cbufA[t] = g_cur[idx + (size_t)t*BH_];
    }

    for (int s = 0; s < S_; s++) {
        // issue next token's loads before the serial chain (MLP=20)
        if (s + 1 < S_) {
            if (LAYER == 1) {
                tokB = g_cur1[(size_t)((s+1)*B_ + b)*H_ + h];
            } else {
#pragma unroll
                for (int t = 0; t < T_; t++)
                    cbufB[t] = g_cur[idx + (size_t)(T_ + t)*BH_];
            }
        }
#pragma unroll
        for (int t = 0; t < T_; t++) {
            float cur = (LAYER == 1) ? tokA : cbufA[t];
            mem = __fsub_rn(__fmaf_rn(0.85f, mem, cur), spk);
            bool fire = (mem > 1.0f);
            spk = fire ? 1.0f : 0.0f;
            rec[idx + (size_t)t*BH_] = spk;
            if (LAYER <= 2) {
                unsigned msk = __ballot_sync(0xffffffffu, fire);
                if (lane == 0) g_mask[(size_t)((s*T_ + t)*B_ + b)*8 + ht] = msk;
            }
            if (LAYER == 3) pc += spk;
        }
        if (LAYER == 3) {
            g_poolh[(size_t)(s*B_ + b)*H_ + h] = __float2half(pc);  // exact int
            pc = 0.f;
        }
        // rotate buffers
        if (LAYER == 1) tokA = tokB;
        else {
#pragma unroll
            for (int t = 0; t < T_; t++) cbufA[t] = cbufB[t];
        }
        idx += (size_t)T_*BH_;
    }
    memOut[base] = mem;
}

// ---------------- batch-mean spikes at masked steps (exact int sums) ----------------
__global__ __launch_bounds__(256) void k_pm(int sel, const float* __restrict__ rec) {
    float* pm = (sel == 0) ? g_pm1 : (sel == 1 ? g_pm2 : g_pm3);
    int m = blockIdx.x;               // 0..NM_-1
    int h = threadIdx.x;
    int step = (m/7)*T_ + (m%7)*3;
    const float* p = rec + (size_t)step*BH_ + h;
    float sum = 0.f;
#pragma unroll
    for (int b = 0; b < B_; b++) sum += p[(size_t)b*H_];   // 0/1 ints: order-free exact
    pm[m*H_ + h] = sum * (1.0f/32.0f);
}

// ---------------- sparse mid GEMM: cur = spk @ W.T + bias ----------------
// Bitwise identical to dense sequential-k fp32: fmaf(0,w,a)=a, fmaf(1,w,a)=RN(a+w).
__global__ __launch_bounds__(256) void k_gemm_sp(int wsel, const float* __restrict__ bias) {
    const float* WT = (wsel == 0) ? g_wt2 : g_wt3;   // [k][n]
    __shared__ float    sW[32*256];                  // 32 KB k-tile
    __shared__ unsigned sM[32];
    const int row0 = blockIdx.x * 32;
    const int n = threadIdx.x;

    float acc[32];
#pragma unroll
    for (int r = 0; r < 32; r++) acc[r] = 0.f;
    float bb = bias[n];

    for (int kt = 0; kt < 8; kt++) {
        const float4* src = (const float4*)(WT + kt*32*256);
        float4* dst = (float4*)sW;
        for (int i = n; i < 32*64; i += 256) dst[i] = src[i];
        if (n < 32) sM[n] = g_mask[(size_t)(row0 + n)*8 + kt];
        __syncthreads();
#pragma unroll
        for (int r = 0; r < 32; r++) {
            unsigned m = sM[r];
            while (m) {
                int k = __ffs(m) - 1;   // smallest set k first (ascending order)
                m &= m - 1;
                acc[r] = __fadd_rn(acc[r], sW[k*256 + n]);
            }
        }
        __syncthreads();
    }
#pragma unroll
    for (int r = 0; r < 32; r++)
        g_cur[(size_t)(row0 + r)*256 + n] = acc[r] + bb;
}

// ---------------- fp16 mma.sync m16n8k16 + ldmatrix helpers ----------------
__device__ __forceinline__ void mma16816(float* d, const uint32_t* a, const uint32_t* b) {
    asm volatile(
        "mma.sync.aligned.m16n8k16.row.col.f32.f16.f16.f32 "
        "{%0,%1,%2,%3},{%4,%5,%6,%7},{%8,%9},{%0,%1,%2,%3};\n"
        : "+f"(d[0]), "+f"(d[1]), "+f"(d[2]), "+f"(d[3])
        : "r"(a[0]), "r"(a[1]), "r"(a[2]), "r"(a[3]), "r"(b[0]), "r"(b[1]));
}
__device__ __forceinline__ void ldsm_x4(uint32_t* r, const __half* p) {
    uint32_t a = (uint32_t)__cvta_generic_to_shared((void*)p);
    asm volatile("ldmatrix.sync.aligned.m8n8.x4.shared.b16 {%0,%1,%2,%3}, [%4];"
        : "=r"(r[0]), "=r"(r[1]), "=r"(r[2]), "=r"(r[3]) : "r"(a));
}

// ---------------- output GEMM: out = (counts . W)/20 + bout  (plain fp16, K=256) ----
__global__ __launch_bounds__(256) void k_gemm_out(const float* __restrict__ bout,
                                                  float* __restrict__ out) {
    __shared__ __half sA[128*72];
    __shared__ __half sB[64*72];
    const int bn = blockIdx.x, bm = blockIdx.y;
    const int tid = threadIdx.x;
    const int warp = tid >> 5, lane = tid & 31;
    const int wm = warp >> 1, wn = warp & 1;       // 4 x 2 warps -> 32m x 32n each
    const int g = lane >> 2, tg = lane & 3;
    const int rsel = (lane & 7) | (lane & 8);      // ldmatrix row within 16
    const int csel = (lane >> 4) << 3;             // ldmatrix k-half select

    float acc[2][4][4] = {};

    for (int kc = 0; kc < 256; kc += 64) {
        for (int u = tid; u < 1024; u += 256) {    // A: 128 rows x 64 halfs
            int row = u >> 3, c8 = (u & 7) * 8;
            *(uint4*)&sA[row*72 + c8] =
                *(const uint4*)&g_poolh[(size_t)(bm*128 + row)*256 + kc + c8];
        }
        for (int u = tid; u < 512; u += 256) {     // B: 64 rows x 64 halfs
            int row = u >> 3, c8 = (u & 7) * 8;
            *(uint4*)&sB[row*72 + c8] =
                *(const uint4*)&g_wouth[(size_t)(bn*64 + row)*256 + kc + c8];
        }
        __syncthreads();
#pragma unroll
        for (int kk = 0; kk < 64; kk += 16) {
            uint32_t afr[2][4], bq[2][4];
#pragma unroll
            for (int mi = 0; mi < 2; mi++)
                ldsm_x4(afr[mi], &sA[(wm*32 + mi*16 + rsel)*72 + kk + csel]);
#pragma unroll
            for (int hb = 0; hb < 2; hb++)
                ldsm_x4(bq[hb], &sB[(wn*32 + hb*16 + rsel)*72 + kk + csel]);
#pragma unroll
            for (int mi = 0; mi < 2; mi++)
#pragma unroll
                for (int ni = 0; ni < 4; ni++) {
                    uint32_t bfr[2] = { bq[ni>>1][ni&1], bq[ni>>1][2 + (ni&1)] };
                    mma16816(acc[mi][ni], afr[mi], bfr);
                }
        }
        __syncthreads();
    }
    const float inv = 1.0f/20.0f;
#pragma unroll
    for (int mi = 0; mi < 2; mi++) {
        int r = bm*128 + wm*32 + mi*16 + g;   // r = s*32 + b ; (r&31)+8 stays < 32
        int s = r >> 5, bb = r & 31;
        size_t base  = (size_t)bb*(size_t)S_*V_ + (size_t)s*V_;
        size_t base8 = base + (size_t)8*(size_t)S_*V_;
#pragma unroll
        for (int ni = 0; ni < 4; ni++) {
            int v = bn*64 + wn*32 + ni*8 + tg*2;
            float b0 = bout[v], b1v = bout[v+1];
            float2 lo = make_float2(acc[mi][ni][0]*inv + b0, acc[mi][ni][1]*inv + b1v);
            float2 hi = make_float2(acc[mi][ni][2]*inv + b0, acc[mi][ni][3]*inv + b1v);
            *(float2*)&out[base  + v] = lo;
            *(float2*)&out[base8 + v] = hi;
        }
    }
}

// ---------------- STDP: d[o,i] = sum_m (A_POST*post)[m,o]*(A_PRE*pre)[m,i] ----------------
__global__ void k_stdp(int sel, float* __restrict__ Dout, int I) {
    const float* Amat = (sel == 0) ? g_pm1 : (sel == 1 ? g_pm2 : g_pm3);
    const float* Bmat = (sel == 0) ? g_xmrep : (sel == 1 ? g_pm1 : g_pm2);
    int o = blockIdx.x;
    int i = threadIdx.x;
    float acc = 0.f;
    for (int m = 0; m < NM_; m++) {
        float a = __fmul_rn(-0.003f, __ldg(&Amat[m*H_ + o]));  // A_POST * post
        float b = __fmul_rn( 0.005f, __ldg(&Bmat[m*I + i]));   // A_PRE * pre
        acc = fmaf(a, b, acc);
    }
    Dout[o*I + i] = acc;
}

// ---------------- launch ----------------
// RULE: never pass a __device__ symbol (g_*) as a kernel argument from here.
extern "C" void kernel_launch(void* const* d_in, const int* in_sizes, int n_in,
                              void* d_out, int out_size) {
    const int*   x     = (const int*)  d_in[0];
    const float* embed = (const float*)d_in[1];
    const float* W1    = (const float*)d_in[2];
    const float* b1    = (const float*)d_in[3];
    const float* W2    = (const float*)d_in[4];
    const float* b2    = (const float*)d_in[5];
    const float* W3    = (const float*)d_in[6];
    const float* b3    = (const float*)d_in[7];
    const float* Wout  = (const float*)d_in[8];
    const float* bout  = (const float*)d_in[9];
    float* out = (float*)d_out;

    (void)in_sizes; (void)n_in; (void)out_size;

    // weight prep
    k_conv_wout<<<(V_*H_ + 255)/256, 256>>>(Wout);
    k_conv_wt  <<<(H_*H_ + 255)/256, 256>>>(W2, W3);

    // layer-1 currents (raw fp32, sequential k) + batch-mean embeddings
    k_cur1 <<<S_, 256>>>(x, embed, W1, b1);
    k_xmrep<<<(NM_*E_ + 255)/256, 256>>>();

    // layer 1
    k_recur<1><<<256, 32>>>(out + OFF_REC1, out + OFF_MEM1);
    k_pm<<<NM_, 256>>>(0, out + OFF_REC1);
    // cur2 = spk1 @ W2.T + b2  (sparse, bit-exact sequential-k)
    k_gemm_sp<<<ROWS_/32, 256>>>(0, b2);
    // layer 2
    k_recur<2><<<256, 32>>>(out + OFF_REC2, out + OFF_MEM2);
    k_pm<<<NM_, 256>>>(1, out + OFF_REC2);
    // cur3 = spk2 @ W3.T + b3
    k_gemm_sp<<<ROWS_/32, 256>>>(1, b3);
    // layer 3 (also builds pooled spike counts)
    k_recur<3><<<256, 32>>>(out + OFF_REC3, out + OFF_MEM3);
    k_pm<<<NM_, 256>>>(2, out + OFF_REC3);

    // out = pooled @ Wout.T + bout  (plain fp16 tensor cores, /20 in epilogue)
    k_gemm_out<<<dim3(V_/64, RQ_/128), 256>>>(bout, out + OFF_OUT);

    // STDP
    k_stdp<<<H_, E_>>>(0, out + OFF_D1, E_);
    k_stdp<<<H_, H_>>>(1, out + OFF_D2, H_);
    k_stdp<<<H_, H_>>>(2, out + OFF_D3, H_);
}

// round 13
// speedup vs baseline: 4.6386x; 1.4967x over previous
#include <cuda_runtime.h>
#include <cuda_fp16.h>
#include <stdint.h>

// ---------------- problem constants ----------------
#define T_  20
#define S_  128
#define B_  32
#define H_  256
#define E_  128
#define V_  32000
#define N_  (S_*T_)      // 2560
#define NM_ (S_*7)       // 896 masked steps
#define ROWS_ (N_*B_)    // 81920
#define RQ_  (S_*B_)     // 4096
#define BH_ (B_*H_)

// ---------------- output layout (floats) ----------------
#define OFF_OUT   0ull
#define OFF_MEM1  131072000ull
#define OFF_MEM2  131080192ull
#define OFF_MEM3  131088384ull
#define OFF_D1    131096576ull
#define OFF_D2    131129344ull
#define OFF_D3    131194880ull
#define OFF_REC1  131260416ull
#define OFF_REC2  152231936ull
#define OFF_REC3  173203456ull

// ---------------- device scratch (static, no runtime alloc) ----------------
__device__ float    g_cur1[RQ_*H_];      //  4 MB  layer-1 currents per token
__device__ float    g_cur [N_*B_*H_];    // 84 MB  currents (reused layer2/3)
__device__ __half   g_wouth[V_*H_];      // 16 MB  fp16 Wout
__device__ __half   g_poolh[RQ_*H_];     // spike counts 0..20, exact in fp16
__device__ float    g_wt2[H_*H_];        // W2 transposed [k][n]
__device__ float    g_wt3[H_*H_];        // W3 transposed [k][n]
__device__ unsigned g_mask[ROWS_*8];     // 2.6 MB spike bitmasks
__device__ float    g_xm[S_*E_];
__device__ float    g_xmrep[NM_*E_];
__device__ float    g_pm1[NM_*H_];
__device__ float    g_pm2[NM_*H_];
__device__ float    g_pm3[NM_*H_];

// ---------------- Wout -> fp16 ----------------
__global__ void k_conv_wout(const float* __restrict__ Wout) {
    int i = blockIdx.x * blockDim.x + threadIdx.x;
    if (i >= V_*H_/2) return;
    float2 w = ((const float2*)Wout)[i];
    __half2 h = __floats2half2_rn(w.x, w.y);
    ((__half2*)g_wouth)[i] = h;
}

// ---------------- W2/W3 transpose [n][k] -> [k][n] ----------------
__global__ void k_conv_wt(const float* __restrict__ W2, const float* __restrict__ W3) {
    int i = blockIdx.x * blockDim.x + threadIdx.x;   // i = k*256 + n
    if (i >= H_*H_) return;
    int n = i & 255, k = i >> 8;
    g_wt2[i] = W2[n*256 + k];
    g_wt3[i] = W3[n*256 + k];
}

// ---------------- layer-1 currents (fp32, sequential k) + batch-mean embedding ----------------
__global__ __launch_bounds__(256) void k_cur1(const int* __restrict__ x,
                                              const float* __restrict__ embed,
                                              const float* __restrict__ W1,
                                              const float* __restrict__ b1) {
    int s = blockIdx.x;
    __shared__ float semb[B_][E_];
    int tid = threadIdx.x;
    for (int u = tid; u < B_*E_; u += 256) {
        int b = u >> 7, e = u & 127;
        semb[b][e] = embed[(size_t)x[b*S_ + s] * E_ + e];
    }
    __syncthreads();
    int h = tid;
    float acc[B_];
#pragma unroll
    for (int b = 0; b < B_; b++) acc[b] = 0.f;
    for (int e = 0; e < E_; e++) {            // strictly increasing k, fp32 FMA
        float w = W1[h*E_ + e];
#pragma unroll
        for (int b = 0; b < B_; b++) acc[b] = fmaf(semb[b][e], w, acc[b]);
    }
    float bb = b1[h];
#pragma unroll
    for (int b = 0; b < B_; b++)
        g_cur1[((s*B_ + b) << 8) + h] = acc[b] + bb;

    if (tid < E_) {                            // batch mean, sequential b order
        float sum = 0.f;
#pragma unroll
        for (int b = 0; b < B_; b++) sum += semb[b][tid];
        g_xm[s*E_ + tid] = sum * (1.0f/32.0f);
    }
}

__global__ void k_xmrep() {
    int i = blockIdx.x * blockDim.x + threadIdx.x;
    if (i >= NM_*E_) return;
    int m = i / E_, e = i % E_;
    g_xmrep[i] = g_xm[(m/7)*E_ + e];
}

// ---------------- LIF recurrence: 1 warp/block, 2-token-ahead prefetch ----------
// mem = fma(0.85, mem, cur) - spk  (bit-identical ops/order to passing version)
template <int LAYER>
__global__ __launch_bounds__(32) void k_recur(float* __restrict__ rec,
                                              float* __restrict__ memOut) {
    const int lane = threadIdx.x;
    const int ht = blockIdx.x & 7;           // h tile
    const int b  = blockIdx.x >> 3;          // batch
    const int h  = ht*32 + lane;

    float mem = 0.f, spk = 0.f;
    const size_t base = (size_t)b * H_ + h;

    constexpr int BUFN = (LAYER == 1) ? 1 : T_;
    float bA[BUFN], bB[BUFN], bC[BUFN];

    auto load_tok = [&](float* cb, int s) {
        if (s >= S_) return;
        if (LAYER == 1) cb[0] = g_cur1[(size_t)(s*B_ + b)*H_ + h];
        else {
#pragma unroll
            for (int t = 0; t < T_; t++) cb[t] = g_cur[base + (size_t)(s*T_ + t)*BH_];
        }
    };
    auto step_tok = [&](float* cb, int s) {
        if (s >= S_) return;
        size_t idx = base + (size_t)(s*T_)*BH_;
        float pc = 0.f;
#pragma unroll
        for (int t = 0; t < T_; t++) {
            float cur = (LAYER == 1) ? cb[0] : cb[t];
            mem = __fsub_rn(__fmaf_rn(0.85f, mem, cur), spk);
            bool fire = (mem > 1.0f);
            spk = fire ? 1.0f : 0.0f;
            rec[idx] = spk;
            if (LAYER <= 2) {
                unsigned msk = __ballot_sync(0xffffffffu, fire);
                if (lane == 0) g_mask[(size_t)((s*T_ + t)*B_ + b)*8 + ht] = msk;
            }
            if (LAYER == 3) pc += spk;
            idx += BH_;
        }
        if (LAYER == 3) g_poolh[(size_t)(s*B_ + b)*H_ + h] = __float2half(pc);
    };

    load_tok(bA, 0);
    load_tok(bB, 1);
    for (int s = 0; s < S_; s += 3) {
        load_tok(bC, s+2);
        step_tok(bA, s);
        load_tok(bA, s+3);
        step_tok(bB, s+1);
        load_tok(bB, s+4);
        step_tok(bC, s+2);
    }
    memOut[base] = mem;
}

// ---------------- batch-mean spikes at masked steps (exact int sums) ----------------
__global__ __launch_bounds__(256) void k_pm(int sel, const float* __restrict__ rec) {
    float* pm = (sel == 0) ? g_pm1 : (sel == 1 ? g_pm2 : g_pm3);
    int m = blockIdx.x;               // 0..NM_-1
    int h = threadIdx.x;
    int step = (m/7)*T_ + (m%7)*3;
    const float* p = rec + (size_t)step*BH_ + h;
    float sum = 0.f;
#pragma unroll
    for (int b = 0; b < B_; b++) sum += p[(size_t)b*H_];   // 0/1 ints: order-free exact
    pm[m*H_ + h] = sum * (1.0f/32.0f);
}

// ---------------- sparse mid GEMM: cur = spk @ W.T + bias ----------------
// Bitwise identical to dense sequential-k fp32: fmaf(0,w,a)=a, fmaf(1,w,a)=RN(a+w).
// 64 rows/block, each thread covers 8 rows x 8 n (two conflict-free LDS.128/bit).
__global__ __launch_bounds__(256) void k_gemm_sp(int wsel, const float* __restrict__ bias) {
    const float* WT = (wsel == 0) ? g_wt2 : g_wt3;   // [k][n]
    __shared__ float    sW[32*256];                  // 32 KB k-tile
    __shared__ unsigned sM[64];
    const int row0 = blockIdx.x * 64;
    const int tid = threadIdx.x;
    const int nlo = (tid & 31) * 4;       // n 0..127 quad
    const int rg  = (tid >> 5) * 8;       // 8 rows per thread

    float4 accL[8], accH[8];
#pragma unroll
    for (int r = 0; r < 8; r++) {
        accL[r] = make_float4(0.f,0.f,0.f,0.f);
        accH[r] = make_float4(0.f,0.f,0.f,0.f);
    }

    for (int kt = 0; kt < 8; kt++) {
        const float4* src = (const float4*)(WT + kt*32*256);
        float4* dst = (float4*)sW;
        for (int i = tid; i < 32*64; i += 256) dst[i] = src[i];
        if (tid < 64) sM[tid] = g_mask[(size_t)(row0 + tid)*8 + kt];
        __syncthreads();
#pragma unroll
        for (int r = 0; r < 8; r++) {
            unsigned m = sM[rg + r];
            float4 aL = accL[r], aH = accH[r];
            while (m) {
                int k = __ffs(m) - 1;            // ascending k: exact order
                m &= m - 1;
                const float* wrow = &sW[k*256];
                float4 w0 = *(const float4*)&wrow[nlo];
                float4 w1 = *(const float4*)&wrow[128 + nlo];
                aL.x = __fadd_rn(aL.x, w0.x); aL.y = __fadd_rn(aL.y, w0.y);
                aL.z = __fadd_rn(aL.z, w0.z); aL.w = __fadd_rn(aL.w, w0.w);
                aH.x = __fadd_rn(aH.x, w1.x); aH.y = __fadd_rn(aH.y, w1.y);
                aH.z = __fadd_rn(aH.z, w1.z); aH.w = __fadd_rn(aH.w, w1.w);
            }
            accL[r] = aL; accH[r] = aH;
        }
        __syncthreads();
    }
    float4 bL = *(const float4*)&bias[nlo];
    float4 bH = *(const float4*)&bias[128 + nlo];
#pragma unroll
    for (int r = 0; r < 8; r++) {
        size_t rowb = (size_t)(row0 + rg + r)*256;
        float4 oL = make_float4(accL[r].x+bL.x, accL[r].y+bL.y, accL[r].z+bL.z, accL[r].w+bL.w);
        float4 oH = make_float4(accH[r].x+bH.x, accH[r].y+bH.y, accH[r].z+bH.z, accH[r].w+bH.w);
        *(float4*)&g_cur[rowb + nlo]       = oL;
        *(float4*)&g_cur[rowb + 128 + nlo] = oH;
    }
}

// ---------------- fp16 mma.sync m16n8k16 + ldmatrix helpers ----------------
__device__ __forceinline__ void mma16816(float* d, const uint32_t* a, const uint32_t* b) {
    asm volatile(
        "mma.sync.aligned.m16n8k16.row.col.f32.f16.f16.f32 "
        "{%0,%1,%2,%3},{%4,%5,%6,%7},{%8,%9},{%0,%1,%2,%3};\n"
        : "+f"(d[0]), "+f"(d[1]), "+f"(d[2]), "+f"(d[3])
        : "r"(a[0]), "r"(a[1]), "r"(a[2]), "r"(a[3]), "r"(b[0]), "r"(b[1]));
}
__device__ __forceinline__ void ldsm_x4(uint32_t* r, const __half* p) {
    uint32_t a = (uint32_t)__cvta_generic_to_shared((void*)p);
    asm volatile("ldmatrix.sync.aligned.m8n8.x4.shared.b16 {%0,%1,%2,%3}, [%4];"
        : "=r"(r[0]), "=r"(r[1]), "=r"(r[2]), "=r"(r[3]) : "r"(a));
}

// ---------------- output GEMM: out = (counts . W)/20 + bout  (fp16, 128x128 tile) ----
__global__ __launch_bounds__(256) void k_gemm_out(const float* __restrict__ bout,
                                                  float* __restrict__ out) {
    __shared__ __half sA[128*72];
    __shared__ __half sB[128*72];
    const int bn = blockIdx.x, bm = blockIdx.y;
    const int tid = threadIdx.x;
    const int warp = tid >> 5, lane = tid & 31;
    const int wm = warp >> 1, wn = warp & 1;       // 4 x 2 warps -> 32m x 64n each
    const int g = lane >> 2, tg = lane & 3;
    const int rsel = (lane & 7) | (lane & 8);      // ldmatrix row within 16
    const int csel = (lane >> 4) << 3;             // ldmatrix k-half select

    float acc[2][8][4] = {};

    for (int kc = 0; kc < 256; kc += 64) {
        for (int u = tid; u < 1024; u += 256) {    // A: 128 rows x 64 halfs
            int row = u >> 3, c8 = (u & 7) * 8;
            *(uint4*)&sA[row*72 + c8] =
                *(const uint4*)&g_poolh[(size_t)(bm*128 + row)*256 + kc + c8];
        }
        for (int u = tid; u < 1024; u += 256) {    // B: 128 rows x 64 halfs
            int row = u >> 3, c8 = (u & 7) * 8;
            *(uint4*)&sB[row*72 + c8] =
                *(const uint4*)&g_wouth[(size_t)(bn*128 + row)*256 + kc + c8];
        }
        __syncthreads();
#pragma unroll
        for (int kk = 0; kk < 64; kk += 16) {
            uint32_t afr[2][4], bq[4][4];
#pragma unroll
            for (int mi = 0; mi < 2; mi++)
                ldsm_x4(afr[mi], &sA[(wm*32 + mi*16 + rsel)*72 + kk + csel]);
#pragma unroll
            for (int nb = 0; nb < 4; nb++)
                ldsm_x4(bq[nb], &sB[(wn*64 + nb*16 + rsel)*72 + kk + csel]);
#pragma unroll
            for (int mi = 0; mi < 2; mi++)
#pragma unroll
                for (int ni = 0; ni < 8; ni++) {
                    uint32_t bfr[2] = { bq[ni>>1][ni&1], bq[ni>>1][2 + (ni&1)] };
                    mma16816(acc[mi][ni], afr[mi], bfr);
                }
        }
        __syncthreads();
    }
    const float inv = 1.0f/20.0f;
#pragma unroll
    for (int mi = 0; mi < 2; mi++) {
        int r = bm*128 + wm*32 + mi*16 + g;   // r = s*32 + b ; (r&31)+8 stays < 32
        int s = r >> 5, bb = r & 31;
        size_t base  = (size_t)bb*(size_t)S_*V_ + (size_t)s*V_;
        size_t base8 = base + (size_t)8*(size_t)S_*V_;
#pragma unroll
        for (int ni = 0; ni < 8; ni++) {
            int v = bn*128 + wn*64 + ni*8 + tg*2;
            float b0 = bout[v], b1v = bout[v+1];
            float2 lo = make_float2(acc[mi][ni][0]*inv + b0, acc[mi][ni][1]*inv + b1v);
            float2 hi = make_float2(acc[mi][ni][2]*inv + b0, acc[mi][ni][3]*inv + b1v);
            *(float2*)&out[base  + v] = lo;
            *(float2*)&out[base8 + v] = hi;
        }
    }
}

// ---------------- STDP: d[o,i] = sum_m (A_POST*post)[m,o]*(A_PRE*pre)[m,i] ----------------
__global__ void k_stdp(int sel, float* __restrict__ Dout, int I) {
    const float* Amat = (sel == 0) ? g_pm1 : (sel == 1 ? g_pm2 : g_pm3);
    const float* Bmat = (sel == 0) ? g_xmrep : (sel == 1 ? g_pm1 : g_pm2);
    int o = blockIdx.x;
    int i = threadIdx.x;
    float acc = 0.f;
    for (int m = 0; m < NM_; m++) {
        float a = __fmul_rn(-0.003f, __ldg(&Amat[m*H_ + o]));  // A_POST * post
        float b = __fmul_rn( 0.005f, __ldg(&Bmat[m*I + i]));   // A_PRE * pre
        acc = fmaf(a, b, acc);
    }
    Dout[o*I + i] = acc;
}

// ---------------- launch ----------------
// RULE: never pass a __device__ symbol (g_*) as a kernel argument from here.
extern "C" void kernel_launch(void* const* d_in, const int* in_sizes, int n_in,
                              void* d_out, int out_size) {
    const int*   x     = (const int*)  d_in[0];
    const float* embed = (const float*)d_in[1];
    const float* W1    = (const float*)d_in[2];
    const float* b1    = (const float*)d_in[3];
    const float* W2    = (const float*)d_in[4];
    const float* b2    = (const float*)d_in[5];
    const float* W3    = (const float*)d_in[6];
    const float* b3    = (const float*)d_in[7];
    const float* Wout  = (const float*)d_in[8];
    const float* bout  = (const float*)d_in[9];
    float* out = (float*)d_out;

    (void)in_sizes; (void)n_in; (void)out_size;

    // weight prep
    k_conv_wout<<<(V_*H_/2 + 255)/256, 256>>>(Wout);
    k_conv_wt  <<<(H_*H_ + 255)/256, 256>>>(W2, W3);

    // layer-1 currents (raw fp32, sequential k) + batch-mean embeddings
    k_cur1 <<<S_, 256>>>(x, embed, W1, b1);
    k_xmrep<<<(NM_*E_ + 255)/256, 256>>>();

    // layer 1
    k_recur<1><<<256, 32>>>(out + OFF_REC1, out + OFF_MEM1);
    k_pm<<<NM_, 256>>>(0, out + OFF_REC1);
    // cur2 = spk1 @ W2.T + b2  (sparse, bit-exact sequential-k)
    k_gemm_sp<<<ROWS_/64, 256>>>(0, b2);
    // layer 2
    k_recur<2><<<256, 32>>>(out + OFF_REC2, out + OFF_MEM2);
    k_pm<<<NM_, 256>>>(1, out + OFF_REC2);
    // cur3 = spk2 @ W3.T + b3
    k_gemm_sp<<<ROWS_/64, 256>>>(1, b3);
    // layer 3 (also builds pooled spike counts)
    k_recur<3><<<256, 32>>>(out + OFF_REC3, out + OFF_MEM3);
    k_pm<<<NM_, 256>>>(2, out + OFF_REC3);

    // out = pooled @ Wout.T + bout  (plain fp16 tensor cores, /20 in epilogue)
    k_gemm_out<<<dim3(V_/128, RQ_/128), 256>>>(bout, out + OFF_OUT);

    // STDP
    k_stdp<<<H_, E_>>>(0, out + OFF_D1, E_);
    k_stdp<<<H_, H_>>>(1, out + OFF_D2, H_);
    k_stdp<<<H_, H_>>>(2, out + OFF_D3, H_);
}